// round 16
// baseline (speedup 1.0000x reference)
#include <cuda_runtime.h>
#include <cuda_bf16.h>
#include <math.h>
#include <stdint.h>

typedef __nv_bfloat16 bf16;

// Problem dimensions (fixed by the reference)
#define B_SZ 16
#define S_SZ 512
#define W_SZ 5
#define D_SZ 200
#define H_SZ 768
#define M1 (B_SZ * S_SZ * W_SZ)   // 40960
#define MQ (B_SZ * S_SZ)          // 8192
#define NMASK (MQ * W_SZ)         // 40960
#define MB1 (M1 / 128)            // 320
#define MBQ (MQ / 128)            // 64
#define WC_SPLIT 6

// Scratch (alloc-free rule: __device__ globals)
__device__ __align__(16) bf16 g_weB [M1 * D_SZ];
__device__ __align__(16) bf16 g_loB [MQ * H_SZ];
__device__ __align__(16) bf16 g_tmpB[M1 * H_SZ];   // zero-init; masked rows stay 0
__device__ __align__(16) bf16 g_ctxB[MQ * H_SZ];
__device__ __align__(16) bf16 g_rB  [MQ * H_SZ];
__device__ __align__(16) bf16 g_W1T [H_SZ * D_SZ];
__device__ __align__(16) bf16 g_W2B [H_SZ * H_SZ];
__device__ __align__(16) bf16 g_W2T [H_SZ * H_SZ];
__device__ __align__(16) bf16 g_aWB [H_SZ * H_SZ];
__device__ __align__(16) bf16 g_WcT [H_SZ * H_SZ];
__device__ __align__(16) float g_wcp[WC_SPLIT * H_SZ * H_SZ];
__device__ float g_agg[MQ * H_SZ];
__device__ int   g_mask_is32;
__device__ int   g_rowmap[M1 + 128];   // compacted (token,word) row indices (+pad)
__device__ int   g_mc_blocks;          // number of 128-row blocks needed

// ---------------------------------------------------------------------------
// conv_all: segmented fp32->bf16 for 4 buffers + mask dtype detect (1 launch)
// ---------------------------------------------------------------------------
#define CN0 (M1 * D_SZ)
#define CN1 (MQ * H_SZ)
#define CN2 (H_SZ * H_SZ)
#define CN3 (H_SZ * H_SZ)
#define CNT (CN0 + CN1 + CN2 + CN3)
#define CONVB (CNT / 4 / 256)
#define DETB ((NMASK / 2 + 255) / 256)

__global__ void conv_all_kernel(const float* __restrict__ p0,
                                const float* __restrict__ p1,
                                const float* __restrict__ p2,
                                const float* __restrict__ p3,
                                const long long* __restrict__ m64)
{
    if (blockIdx.x >= CONVB) {
        int i = (blockIdx.x - CONVB) * 256 + threadIdx.x;
        if (i < NMASK / 2) {
            unsigned long long v = (unsigned long long)m64[i];
            if (v > 1ULL) atomicOr(&g_mask_is32, 1);
        }
        return;
    }
    long idx = ((long)blockIdx.x * 256 + threadIdx.x) * 4;
    const float* in;
    bf16* out;
    long off;
    if (idx < CN0)                    { in = p0; out = g_weB; off = idx; }
    else if (idx < CN0 + CN1)         { in = p1; out = g_loB; off = idx - CN0; }
    else if (idx < CN0 + CN1 + CN2)   { in = p2; out = g_W2B; off = idx - CN0 - CN1; }
    else                              { in = p3; out = g_aWB; off = idx - CN0 - CN1 - CN2; }
    float4 v = *reinterpret_cast<const float4*>(in + off);
    *reinterpret_cast<__nv_bfloat162*>(out + off)     = __floats2bfloat162_rn(v.x, v.y);
    *reinterpret_cast<__nv_bfloat162*>(out + off + 2) = __floats2bfloat162_rn(v.z, v.w);
}

// ---------------------------------------------------------------------------
// mask_compact: build row map of needed (token,word) rows.
// keep word w of token t iff mask!=0, or ALL words of t are masked (softmax
// then needs real scores for all 5). Single block, deterministic prefix scan.
// ---------------------------------------------------------------------------
__global__ __launch_bounds__(1024)
void mask_compact(const void* __restrict__ mraw)
{
    __shared__ int s_warp[32];
    const int tid = threadIdx.x;            // 0..1023, each owns 8 tokens
    const bool is32 = (g_mask_is32 != 0);

    int kw[8];
    int cnt = 0;
    #pragma unroll
    for (int i = 0; i < 8; i++) {
        int tk = tid * 8 + i;
        int bits = 0;
        #pragma unroll
        for (int w = 0; w < W_SZ; w++) {
            long long mv = is32
                ? (long long)((const int*)mraw)[(size_t)tk * W_SZ + w]
                : ((const long long*)mraw)[(size_t)tk * W_SZ + w];
            if (mv != 0) bits |= (1 << w);
        }
        if (bits == 0) bits = 31;           // all-masked token: keep all 5
        kw[i] = bits;
        cnt += __popc(bits);
    }

    // exclusive scan of cnt over 1024 threads
    const int lane = tid & 31, wrp = tid >> 5;
    int inc = cnt;
    #pragma unroll
    for (int off = 1; off < 32; off <<= 1) {
        int n = __shfl_up_sync(0xffffffff, inc, off);
        if (lane >= off) inc += n;
    }
    if (lane == 31) s_warp[wrp] = inc;
    __syncthreads();
    if (wrp == 0) {
        int wv = s_warp[lane];
        #pragma unroll
        for (int off = 1; off < 32; off <<= 1) {
            int n = __shfl_up_sync(0xffffffff, wv, off);
            if (lane >= off) wv += n;
        }
        s_warp[lane] = wv;                   // inclusive warp sums
    }
    __syncthreads();

    int base = inc - cnt + (wrp ? s_warp[wrp - 1] : 0);
    #pragma unroll
    for (int i = 0; i < 8; i++) {
        int tk = tid * 8 + i;
        int bits = kw[i];
        while (bits) {
            int w = __ffs(bits) - 1;
            bits &= bits - 1;
            g_rowmap[base++] = tk * W_SZ + w;
        }
    }

    if (tid == 1023) {
        int total = base;                    // grand total
        int nb = (total + 127) >> 7;
        g_mc_blocks = nb;
        for (int i = total; i < nb * 128; i++)
            g_rowmap[i] = 0;                 // pad: duplicates row 0 (benign)
    }
}

// ---------------------------------------------------------------------------
// One transpose+convert launch for W1 and W2 (z selects)
// ---------------------------------------------------------------------------
__global__ void trans_all_kernel(const float* __restrict__ W1,
                                 const float* __restrict__ W2)
{
    const int z = blockIdx.z;
    const float* in = z ? W2 : W1;
    bf16* out = z ? g_W2T : g_W1T;
    const int K = z ? H_SZ : D_SZ;
    const int N = H_SZ;
    if (blockIdx.y * 32 >= K) return;

    __shared__ float tile[32][33];
    int x = blockIdx.x * 32 + threadIdx.x;
    int y0 = blockIdx.y * 32;
    #pragma unroll
    for (int j = 0; j < 32; j += 8) {
        int y = y0 + threadIdx.y + j;
        if (y < K && x < N)
            tile[threadIdx.y + j][threadIdx.x] = in[(size_t)y * N + x];
    }
    __syncthreads();
    int ox = y0 + threadIdx.x;
    int oy0 = blockIdx.x * 32;
    #pragma unroll
    for (int j = 0; j < 32; j += 8) {
        int oy = oy0 + threadIdx.y + j;
        if (oy < N && ox < K)
            out[(size_t)oy * K + ox] =
                __float2bfloat16_rn(tile[threadIdx.x][threadIdx.y + j]);
    }
}

// ---------------------------------------------------------------------------
// Shared GEMM machinery
// ---------------------------------------------------------------------------
#define BKQ 64
#define TSTRIDE 72
#define TILE_BF (128 * TSTRIDE)
#define SMEM_BYTES (4 * TILE_BF * 2)     // 73728 B -> 3 CTAs/SM

__device__ __forceinline__ void cp_async16(uint32_t dst, const void* src, int ssize)
{
    asm volatile("cp.async.cg.shared.global [%0], [%1], 16, %2;\n"
                 :: "r"(dst), "l"(src), "r"(ssize));
}
__device__ __forceinline__ void cp_commit() { asm volatile("cp.async.commit_group;\n"); }
__device__ __forceinline__ void cp_wait0()  { asm volatile("cp.async.wait_group 0;\n"); }

#define MMA_BF16(acc, af, bf0, bf1)                                            \
    asm volatile(                                                              \
        "mma.sync.aligned.m16n8k16.row.col.f32.bf16.bf16.f32 "                 \
        "{%0,%1,%2,%3}, {%4,%5,%6,%7}, {%8,%9}, {%0,%1,%2,%3};\n"              \
        : "+f"((acc)[0]), "+f"((acc)[1]), "+f"((acc)[2]), "+f"((acc)[3])       \
        : "r"((af)[0]), "r"((af)[1]), "r"((af)[2]), "r"((af)[3]),              \
          "r"(bf0), "r"(bf1))

#define GEMM_VARS()                                                            \
    const int tid  = threadIdx.x;                                              \
    const int lane = tid & 31;                                                 \
    const int wid  = tid >> 5;                                                 \
    const int wm   = (wid & 1) * 64;                                           \
    const int wn   = (wid >> 1) * 64;                                          \
    const int g    = lane >> 2;                                                \
    const int tg   = lane & 3;                                                 \
    const int crow = tid >> 3;                                                 \
    const int ac   = (tid & 7) * 8;

#define GEMM_BODY(A, Bt, LDA, K, m0, n0)                                       \
    uint32_t as_base[2], bs_base[2];                                           \
    as_base[0] = (uint32_t)__cvta_generic_to_shared(As[0]);                    \
    as_base[1] = (uint32_t)__cvta_generic_to_shared(As[1]);                    \
    bs_base[0] = (uint32_t)__cvta_generic_to_shared(Bs[0]);                    \
    bs_base[1] = (uint32_t)__cvta_generic_to_shared(Bs[1]);                    \
    float acc[4][8][4];                                                        \
    _Pragma("unroll")                                                          \
    for (int mi = 0; mi < 4; mi++)                                             \
        _Pragma("unroll")                                                      \
        for (int ni = 0; ni < 8; ni++)                                         \
            _Pragma("unroll")                                                  \
            for (int r = 0; r < 4; r++)                                        \
                acc[mi][ni][r] = 0.f;                                          \
    const int kt16  = ((K) + 15) >> 4;                                         \
    const int tiles = (kt16 + 3) >> 2;                                         \
    auto load_tile = [&](int buf, int k0) {                                    \
        int gk = k0 + ac;                                                      \
        int ok = (gk < (K)) ? 16 : 0;                                          \
        int gks = ok ? gk : 0;                                                 \
        _Pragma("unroll")                                                      \
        for (int i = 0; i < 8; i++) {                                          \
            int row = crow + 16 * i;                                           \
            cp_async16(as_base[buf] + (row * TSTRIDE + ac) * 2,                \
                       (A) + (size_t)((m0) + row) * (LDA) + gks, ok);          \
        }                                                                      \
        _Pragma("unroll")                                                      \
        for (int i = 0; i < 8; i++) {                                          \
            int row = crow + 16 * i;                                           \
            cp_async16(bs_base[buf] + (row * TSTRIDE + ac) * 2,                \
                       (Bt) + (size_t)((n0) + row) * (LDA) + gks, ok);         \
        }                                                                      \
        cp_commit();                                                           \
    };                                                                         \
    load_tile(0, 0);                                                           \
    int buf = 0;                                                               \
    for (int t = 0; t < tiles; t++) {                                          \
        cp_wait0();                                                            \
        __syncthreads();                                                       \
        if (t + 1 < tiles)                                                     \
            load_tile(buf ^ 1, (t + 1) * BKQ);                                 \
        const bf16* Ab = As[buf];                                              \
        const bf16* Bb = Bs[buf];                                              \
        const int slim = kt16 - (t << 2);                                      \
        _Pragma("unroll")                                                      \
        for (int s = 0; s < 4; s++) {                                          \
            if (s >= slim) break;                                              \
            const int kb = s * 16;                                             \
            uint32_t af[4][4];                                                 \
            _Pragma("unroll")                                                  \
            for (int mi = 0; mi < 4; mi++) {                                   \
                const bf16* p = Ab + (wm + mi * 16 + g) * TSTRIDE + kb + 2 * tg; \
                af[mi][0] = *reinterpret_cast<const uint32_t*>(p);             \
                af[mi][1] = *reinterpret_cast<const uint32_t*>(p + 8 * TSTRIDE); \
                af[mi][2] = *reinterpret_cast<const uint32_t*>(p + 8);         \
                af[mi][3] = *reinterpret_cast<const uint32_t*>(p + 8 * TSTRIDE + 8); \
            }                                                                  \
            uint32_t bfr[8][2];                                                \
            _Pragma("unroll")                                                  \
            for (int ni = 0; ni < 8; ni++) {                                   \
                const bf16* p = Bb + (wn + ni * 8 + g) * TSTRIDE + kb + 2 * tg; \
                bfr[ni][0] = *reinterpret_cast<const uint32_t*>(p);            \
                bfr[ni][1] = *reinterpret_cast<const uint32_t*>(p + 8);        \
            }                                                                  \
            _Pragma("unroll")                                                  \
            for (int mi = 0; mi < 4; mi++)                                     \
                _Pragma("unroll")                                              \
                for (int ni = 0; ni < 8; ni++)                                 \
                    MMA_BF16(acc[mi][ni], af[mi], bfr[ni][0], bfr[ni][1]);     \
        }                                                                      \
        buf ^= 1;                                                              \
    }

// ---------------------------------------------------------------------------
// Wc split-K GEMM + reduce
// ---------------------------------------------------------------------------
__global__ __launch_bounds__(128, 3)
void wc_gemm(void)
{
    extern __shared__ bf16 smem[];
    bf16* As[2] = { smem,                smem + TILE_BF };
    bf16* Bs[2] = { smem + 2 * TILE_BF,  smem + 3 * TILE_BF };
    GEMM_VARS();
    const int m0 = blockIdx.y * 128;
    const int n0 = blockIdx.x * 128;
    const int z  = blockIdx.z;
    const bf16* A  = g_W2B + z * 128;
    const bf16* Bt = g_aWB + z * 128;
    GEMM_BODY(A, Bt, H_SZ, 128, m0, n0);

    float* P = g_wcp + (size_t)z * H_SZ * H_SZ;
    #pragma unroll
    for (int ni = 0; ni < 8; ni++) {
        const int col = n0 + wn + ni * 8 + tg * 2;
        #pragma unroll
        for (int mi = 0; mi < 4; mi++) {
            const int row = m0 + wm + mi * 16 + g;
            *reinterpret_cast<float2*>(&P[(size_t)row * H_SZ + col]) =
                make_float2(acc[mi][ni][0], acc[mi][ni][1]);
            *reinterpret_cast<float2*>(&P[(size_t)(row + 8) * H_SZ + col]) =
                make_float2(acc[mi][ni][2], acc[mi][ni][3]);
        }
    }
}

__global__ void wc_reduce(void)
{
    int i = (blockIdx.x * blockDim.x + threadIdx.x) * 2;
    if (i >= H_SZ * H_SZ) return;
    float2 s = *reinterpret_cast<const float2*>(g_wcp + i);
    #pragma unroll
    for (int z = 1; z < WC_SPLIT; z++) {
        float2 p = *reinterpret_cast<const float2*>(g_wcp + (size_t)z * H_SZ * H_SZ + i);
        s.x += p.x; s.y += p.y;
    }
    *reinterpret_cast<__nv_bfloat162*>(g_WcT + i) = __floats2bfloat162_rn(s.x, s.y);
}

// ---------------------------------------------------------------------------
// GEMM1 (gathered): for compacted rows only.
// tmpB[rowmap[i]] = bf16(tanh(weB[rowmap[i]] @ W1T^T + b1))
// grid (6, MB1) fixed; blocks beyond g_mc_blocks early-exit.
// ---------------------------------------------------------------------------
__global__ __launch_bounds__(128, 3)
void gemm1(const float* __restrict__ b1)
{
    if ((int)blockIdx.y >= g_mc_blocks) return;
    extern __shared__ bf16 smem[];
    bf16* As[2] = { smem,                smem + TILE_BF };
    bf16* Bs[2] = { smem + 2 * TILE_BF,  smem + 3 * TILE_BF };
    GEMM_VARS();
    const int n0 = blockIdx.x * 128;
    const int m0 = blockIdx.y * 128;

    // Gathered A row indices for the loader
    int grow[8];
    #pragma unroll
    for (int i = 0; i < 8; i++)
        grow[i] = g_rowmap[m0 + crow + 16 * i];

    uint32_t as_base[2], bs_base[2];
    as_base[0] = (uint32_t)__cvta_generic_to_shared(As[0]);
    as_base[1] = (uint32_t)__cvta_generic_to_shared(As[1]);
    bs_base[0] = (uint32_t)__cvta_generic_to_shared(Bs[0]);
    bs_base[1] = (uint32_t)__cvta_generic_to_shared(Bs[1]);

    float acc[4][8][4];
    #pragma unroll
    for (int mi = 0; mi < 4; mi++)
        #pragma unroll
        for (int ni = 0; ni < 8; ni++)
            #pragma unroll
            for (int r = 0; r < 4; r++)
                acc[mi][ni][r] = 0.f;

    const int K = D_SZ;
    const int kt16  = (K + 15) >> 4;     // 13
    const int tiles = (kt16 + 3) >> 2;   // 4

    auto load_tile = [&](int buf, int k0) {
        int gk = k0 + ac;
        int ok = (gk < K) ? 16 : 0;
        int gks = ok ? gk : 0;
        #pragma unroll
        for (int i = 0; i < 8; i++) {
            int row = crow + 16 * i;
            cp_async16(as_base[buf] + (row * TSTRIDE + ac) * 2,
                       g_weB + (size_t)grow[i] * K + gks, ok);
        }
        #pragma unroll
        for (int i = 0; i < 8; i++) {
            int row = crow + 16 * i;
            cp_async16(bs_base[buf] + (row * TSTRIDE + ac) * 2,
                       g_W1T + (size_t)(n0 + row) * K + gks, ok);
        }
        cp_commit();
    };

    load_tile(0, 0);
    int buf = 0;
    for (int t = 0; t < tiles; t++) {
        cp_wait0();
        __syncthreads();
        if (t + 1 < tiles)
            load_tile(buf ^ 1, (t + 1) * BKQ);
        const bf16* Ab = As[buf];
        const bf16* Bb = Bs[buf];
        const int slim = kt16 - (t << 2);
        #pragma unroll
        for (int s = 0; s < 4; s++) {
            if (s >= slim) break;
            const int kb = s * 16;
            uint32_t af[4][4];
            #pragma unroll
            for (int mi = 0; mi < 4; mi++) {
                const bf16* p = Ab + (wm + mi * 16 + g) * TSTRIDE + kb + 2 * tg;
                af[mi][0] = *reinterpret_cast<const uint32_t*>(p);
                af[mi][1] = *reinterpret_cast<const uint32_t*>(p + 8 * TSTRIDE);
                af[mi][2] = *reinterpret_cast<const uint32_t*>(p + 8);
                af[mi][3] = *reinterpret_cast<const uint32_t*>(p + 8 * TSTRIDE + 8);
            }
            uint32_t bfr[8][2];
            #pragma unroll
            for (int ni = 0; ni < 8; ni++) {
                const bf16* p = Bb + (wn + ni * 8 + g) * TSTRIDE + kb + 2 * tg;
                bfr[ni][0] = *reinterpret_cast<const uint32_t*>(p);
                bfr[ni][1] = *reinterpret_cast<const uint32_t*>(p + 8);
            }
            #pragma unroll
            for (int mi = 0; mi < 4; mi++)
                #pragma unroll
                for (int ni = 0; ni < 8; ni++)
                    MMA_BF16(acc[mi][ni], af[mi], bfr[ni][0], bfr[ni][1]);
        }
        buf ^= 1;
    }

    // Scatter epilogue via rowmap
    #pragma unroll
    for (int ni = 0; ni < 8; ni++) {
        const int col = n0 + wn + ni * 8 + tg * 2;
        const float b0 = b1[col];
        const float bb1 = b1[col + 1];
        #pragma unroll
        for (int mi = 0; mi < 4; mi++) {
            const int lrow = wm + mi * 16 + g;
            const int orow0 = g_rowmap[m0 + lrow];
            const int orow1 = g_rowmap[m0 + lrow + 8];
            float r0 = tanhf(acc[mi][ni][0] + b0);
            float r1 = tanhf(acc[mi][ni][1] + bb1);
            float r2 = tanhf(acc[mi][ni][2] + b0);
            float r3 = tanhf(acc[mi][ni][3] + bb1);
            *reinterpret_cast<__nv_bfloat162*>(&g_tmpB[(size_t)orow0 * H_SZ + col]) =
                __floats2bfloat162_rn(r0, r1);
            *reinterpret_cast<__nv_bfloat162*>(&g_tmpB[(size_t)orow1 * H_SZ + col]) =
                __floats2bfloat162_rn(r2, r3);
        }
    }
}

// ---------------------------------------------------------------------------
// GEMM_r: rB = bf16(loB @ WcT^T), K=768. grid (6, MBQ)
// ---------------------------------------------------------------------------
__global__ __launch_bounds__(128, 3)
void gemm_r(void)
{
    extern __shared__ bf16 smem[];
    bf16* As[2] = { smem,                smem + TILE_BF };
    bf16* Bs[2] = { smem + 2 * TILE_BF,  smem + 3 * TILE_BF };
    GEMM_VARS();
    const int n0 = blockIdx.x * 128;
    const int m0 = blockIdx.y * 128;
    GEMM_BODY(g_loB, g_WcT, H_SZ, H_SZ, m0, n0);

    #pragma unroll
    for (int ni = 0; ni < 8; ni++) {
        const int col = n0 + wn + ni * 8 + tg * 2;
        #pragma unroll
        for (int mi = 0; mi < 4; mi++) {
            const int row = m0 + wm + mi * 16 + g;
            *reinterpret_cast<__nv_bfloat162*>(&g_rB[(size_t)row * H_SZ + col]) =
                __floats2bfloat162_rn(acc[mi][ni][0], acc[mi][ni][1]);
            *reinterpret_cast<__nv_bfloat162*>(&g_rB[(size_t)(row + 8) * H_SZ + col]) =
                __floats2bfloat162_rn(acc[mi][ni][2], acc[mi][ni][3]);
        }
    }
}

// ---------------------------------------------------------------------------
// GEMM_agg: agg = ctx @ W2 + b2 (fp32 out). grid (6, MBQ)
// ---------------------------------------------------------------------------
__global__ __launch_bounds__(128, 3)
void gemm_agg(const float* __restrict__ b2)
{
    extern __shared__ bf16 smem[];
    bf16* As[2] = { smem,                smem + TILE_BF };
    bf16* Bs[2] = { smem + 2 * TILE_BF,  smem + 3 * TILE_BF };
    GEMM_VARS();
    const int n0 = blockIdx.x * 128;
    const int m0 = blockIdx.y * 128;
    GEMM_BODY(g_ctxB, g_W2T, H_SZ, H_SZ, m0, n0);

    #pragma unroll
    for (int ni = 0; ni < 8; ni++) {
        const int col = n0 + wn + ni * 8 + tg * 2;
        const float b0 = b2[col];
        const float bb1 = b2[col + 1];
        #pragma unroll
        for (int mi = 0; mi < 4; mi++) {
            const int row = m0 + wm + mi * 16 + g;
            *reinterpret_cast<float2*>(&g_agg[(size_t)row * H_SZ + col]) =
                make_float2(acc[mi][ni][0] + b0, acc[mi][ni][1] + bb1);
            *reinterpret_cast<float2*>(&g_agg[(size_t)(row + 8) * H_SZ + col]) =
                make_float2(acc[mi][ni][2] + b0, acc[mi][ni][3] + bb1);
        }
    }
}

// ---------------------------------------------------------------------------
// Attention kernel (masked rows of g_tmpB are all-zero; alpha for them
// underflows to exact 0, matching the reference bit-for-bit)
// ---------------------------------------------------------------------------
__global__ __launch_bounds__(256)
void attn_kernel(const void* __restrict__ mask, bf16* __restrict__ ctxB)
{
    const int bs  = blockIdx.x;
    const int tid = threadIdx.x;

    __shared__ float red[5][256];
    __shared__ float s_alpha[5];

    const bf16* rrow = g_rB   + (size_t)bs * H_SZ;
    const bf16* trow = g_tmpB + (size_t)bs * W_SZ * H_SZ;

    float rv[3], tv[5][3];
    #pragma unroll
    for (int e = 0; e < 3; e++) {
        int h = tid + e * 256;
        rv[e] = __bfloat162float(rrow[h]);
        #pragma unroll
        for (int w = 0; w < W_SZ; w++)
            tv[w][e] = __bfloat162float(trow[w * H_SZ + h]);
    }

    #pragma unroll
    for (int w = 0; w < W_SZ; w++) {
        float d = 0.f;
        #pragma unroll
        for (int e = 0; e < 3; e++)
            d = fmaf(rv[e], tv[w][e], d);
        red[w][tid] = d;
    }
    __syncthreads();
    for (int s = 128; s > 0; s >>= 1) {
        if (tid < s) {
            #pragma unroll
            for (int w = 0; w < W_SZ; w++)
                red[w][tid] += red[w][tid + s];
        }
        __syncthreads();
    }

    if (tid == 0) {
        const bool is32 = (g_mask_is32 != 0);
        float sc[5];
        float mx = -1e30f;
        #pragma unroll
        for (int w = 0; w < W_SZ; w++) {
            float mk = is32
                ? (float)((const int*)mask)[(size_t)bs * W_SZ + w]
                : (float)((const long long*)mask)[(size_t)bs * W_SZ + w];
            sc[w] = red[w][0] + (1.f - mk) * (-10000.f);
            mx = fmaxf(mx, sc[w]);
        }
        float sum = 0.f;
        #pragma unroll
        for (int w = 0; w < W_SZ; w++) {
            sc[w] = expf(sc[w] - mx);
            sum += sc[w];
        }
        float inv = 1.f / sum;
        #pragma unroll
        for (int w = 0; w < W_SZ; w++)
            s_alpha[w] = sc[w] * inv;
    }
    __syncthreads();

    float alpha[5];
    #pragma unroll
    for (int w = 0; w < W_SZ; w++) alpha[w] = s_alpha[w];

    #pragma unroll
    for (int e = 0; e < 3; e++) {
        int h = tid + e * 256;
        float c = 0.f;
        #pragma unroll
        for (int w = 0; w < W_SZ; w++)
            c = fmaf(alpha[w], tv[w][e], c);
        ctxB[(size_t)bs * H_SZ + h] = __float2bfloat16_rn(c);
    }
}

// ---------------------------------------------------------------------------
// Residual + LayerNorm
// ---------------------------------------------------------------------------
__global__ __launch_bounds__(256)
void ln_kernel(const float* __restrict__ lo,
               const float* __restrict__ gamma,
               const float* __restrict__ beta,
               float* __restrict__ out)
{
    const int bs  = blockIdx.x;
    const int tid = threadIdx.x;

    __shared__ float red0[256], red1[256];

    const float* lorow = lo    + (size_t)bs * H_SZ;
    const float* agrow = g_agg + (size_t)bs * H_SZ;

    float hv[3];
    float psum = 0.f, psq = 0.f;
    #pragma unroll
    for (int e = 0; e < 3; e++) {
        int h = tid + e * 256;
        hv[e] = lorow[h] + agrow[h];
        psum += hv[e];
        psq  = fmaf(hv[e], hv[e], psq);
    }
    red0[tid] = psum;
    red1[tid] = psq;
    __syncthreads();
    for (int s = 128; s > 0; s >>= 1) {
        if (tid < s) {
            red0[tid] += red0[tid + s];
            red1[tid] += red1[tid + s];
        }
        __syncthreads();
    }

    const float inv_h = 1.f / (float)H_SZ;
    float mu   = red0[0] * inv_h;
    float var  = red1[0] * inv_h - mu * mu;
    float rstd = rsqrtf(var + 1e-12f);

    #pragma unroll
    for (int e = 0; e < 3; e++) {
        int h = tid + e * 256;
        out[(size_t)bs * H_SZ + h] = (hv[e] - mu) * rstd * gamma[h] + beta[h];
    }
}

// ---------------------------------------------------------------------------
// Launch (R12/R15 structure + mask compaction before gemm1):
//  s0: memset, conv ─ evConv ─ compact ─ trans ─ gemm1 ─ (wait evR) attn, agg, ln
//  s1: (wait evConv) wc_gemm ─ wc_reduce ─ gemm_r ─ evR
// ---------------------------------------------------------------------------
extern "C" void kernel_launch(void* const* d_in, const int* in_sizes, int n_in,
                              void* d_out, int out_size)
{
    const float* lo     = (const float*)d_in[0];
    const float* we_in  = (const float*)d_in[1];
    const void*  mask   = d_in[2];
    const float* W1     = (const float*)d_in[3];
    const float* b1     = (const float*)d_in[4];
    const float* W2     = (const float*)d_in[5];
    const float* b2     = (const float*)d_in[6];
    const float* attn_W = (const float*)d_in[7];
    const float* gamma  = (const float*)d_in[8];
    const float* beta   = (const float*)d_in[9];
    float*       out    = (float*)d_out;

    bf16 *ctxB_p;
    cudaGetSymbolAddress((void**)&ctxB_p, g_ctxB);

    cudaFuncSetAttribute(wc_gemm,  cudaFuncAttributeMaxDynamicSharedMemorySize, SMEM_BYTES);
    cudaFuncSetAttribute(gemm1,    cudaFuncAttributeMaxDynamicSharedMemorySize, SMEM_BYTES);
    cudaFuncSetAttribute(gemm_r,   cudaFuncAttributeMaxDynamicSharedMemorySize, SMEM_BYTES);
    cudaFuncSetAttribute(gemm_agg, cudaFuncAttributeMaxDynamicSharedMemorySize, SMEM_BYTES);

    int* flag_p;
    cudaGetSymbolAddress((void**)&flag_p, g_mask_is32);

    cudaStream_t s1;
    cudaStreamCreateWithFlags(&s1, cudaStreamNonBlocking);
    cudaEvent_t evConv, evR;
    cudaEventCreateWithFlags(&evConv, cudaEventDisableTiming);
    cudaEventCreateWithFlags(&evR,    cudaEventDisableTiming);

    dim3 blk(128);

    // ---- s0: preprocessing ----
    cudaMemsetAsync(flag_p, 0, sizeof(int));
    conv_all_kernel<<<CONVB + DETB, 256>>>(we_in, lo, W2, attn_W,
                                           (const long long*)mask);
    cudaEventRecord(evConv, 0);

    // ---- s1: Wc chain + GEMM_r (needs conv outputs only) ----
    cudaStreamWaitEvent(s1, evConv, 0);
    wc_gemm<<<dim3(6, 6, WC_SPLIT), blk, SMEM_BYTES, s1>>>();
    wc_reduce<<<(H_SZ * H_SZ / 2 + 255) / 256, 256, 0, s1>>>();
    gemm_r<<<dim3(6, MBQ), blk, SMEM_BYTES, s1>>>();
    cudaEventRecord(evR, s1);

    // ---- s0: mask compaction, transposes, gathered GEMM1 ----
    mask_compact<<<1, 1024>>>(mask);
    {
        dim3 tb(32, 8);
        dim3 tg(24, 24, 2);
        trans_all_kernel<<<tg, tb>>>(W1, W2);
    }
    gemm1<<<dim3(6, MB1), blk, SMEM_BYTES>>>(b1);

    // ---- join, then the dependent tail ----
    cudaStreamWaitEvent(0, evR, 0);
    attn_kernel<<<MQ, 256>>>(mask, ctxB_p);
    gemm_agg<<<dim3(6, MBQ), blk, SMEM_BYTES>>>(b2);
    ln_kernel<<<MQ, 256>>>(lo, gamma, beta, out);

    cudaStreamDestroy(s1);
    cudaEventDestroy(evConv);
    cudaEventDestroy(evR);
}

// round 17
// speedup vs baseline: 1.0502x; 1.0502x over previous
#include <cuda_runtime.h>
#include <cuda_bf16.h>
#include <math.h>
#include <stdint.h>

typedef __nv_bfloat16 bf16;

// Problem dimensions (fixed by the reference)
#define B_SZ 16
#define S_SZ 512
#define W_SZ 5
#define D_SZ 200
#define H_SZ 768
#define M1 (B_SZ * S_SZ * W_SZ)   // 40960
#define MQ (B_SZ * S_SZ)          // 8192
#define NMASK (MQ * W_SZ)         // 40960
#define MB1 (M1 / 128)            // 320
#define MBQ (MQ / 128)            // 64
#define WC_SPLIT 6

// Scratch (alloc-free rule: __device__ globals)
__device__ __align__(16) bf16 g_weB [M1 * D_SZ];
__device__ __align__(16) bf16 g_loB [MQ * H_SZ];
__device__ __align__(16) bf16 g_tmpB[M1 * H_SZ];   // zero-init; masked rows stay 0
__device__ __align__(16) bf16 g_ctxB[MQ * H_SZ];
__device__ __align__(16) bf16 g_rB  [MQ * H_SZ];
__device__ __align__(16) bf16 g_W1T [H_SZ * D_SZ];
__device__ __align__(16) bf16 g_W2B [H_SZ * H_SZ];
__device__ __align__(16) bf16 g_W2T [H_SZ * H_SZ];
__device__ __align__(16) bf16 g_aWB [H_SZ * H_SZ];
__device__ __align__(16) bf16 g_WcT [H_SZ * H_SZ];
__device__ __align__(16) float g_wcp[WC_SPLIT * H_SZ * H_SZ];
__device__ float g_agg[MQ * H_SZ];
__device__ int   g_mask_is32;
__device__ int   g_rowmap[M1 + 128];   // compacted (token,word) row indices (+pad)
__device__ int   g_mc_blocks;          // number of 128-row blocks needed

// ---------------------------------------------------------------------------
// conv_all: segmented fp32->bf16 for 4 buffers (1 launch; no detect blocks)
// ---------------------------------------------------------------------------
#define CN0 (M1 * D_SZ)
#define CN1 (MQ * H_SZ)
#define CN2 (H_SZ * H_SZ)
#define CN3 (H_SZ * H_SZ)
#define CNT (CN0 + CN1 + CN2 + CN3)
#define CONVB (CNT / 4 / 256)

__global__ void conv_all_kernel(const float* __restrict__ p0,
                                const float* __restrict__ p1,
                                const float* __restrict__ p2,
                                const float* __restrict__ p3)
{
    long idx = ((long)blockIdx.x * 256 + threadIdx.x) * 4;
    if (idx >= CNT) return;
    const float* in;
    bf16* out;
    long off;
    if (idx < CN0)                    { in = p0; out = g_weB; off = idx; }
    else if (idx < CN0 + CN1)         { in = p1; out = g_loB; off = idx - CN0; }
    else if (idx < CN0 + CN1 + CN2)   { in = p2; out = g_W2B; off = idx - CN0 - CN1; }
    else                              { in = p3; out = g_aWB; off = idx - CN0 - CN1 - CN2; }
    float4 v = *reinterpret_cast<const float4*>(in + off);
    *reinterpret_cast<__nv_bfloat162*>(out + off)     = __floats2bfloat162_rn(v.x, v.y);
    *reinterpret_cast<__nv_bfloat162*>(out + off + 2) = __floats2bfloat162_rn(v.z, v.w);
}

// ---------------------------------------------------------------------------
// mask_compact: self-contained. Detects mask dtype (int32 vs int64) via a
// block-local reduce (reads bounded to the int32 buffer size), writes
// g_mask_is32, then builds the compacted row map: keep word w of token t iff
// mask!=0, or ALL words of t are masked. Single block, deterministic scan.
// Launched concurrent with conv_all (disjoint inputs) — off the critical path.
// ---------------------------------------------------------------------------
__global__ __launch_bounds__(1024)
void mask_compact(const void* __restrict__ mraw)
{
    __shared__ int s_warp[32];
    __shared__ int s_is32;
    const int tid = threadIdx.x;            // 0..1023, each owns 8 tokens
    if (tid == 0) s_is32 = 0;
    __syncthreads();

    // dtype detection: if genuinely int64 (values 0/1), all v <= 1; if int32,
    // packed pairs produce values >= 2^32 with near-certainty.
    const long long* m64 = (const long long*)mraw;
    bool any = false;
    for (int i = tid; i < NMASK / 2; i += 1024)
        if ((unsigned long long)m64[i] > 1ULL) { any = true; break; }
    if (any) s_is32 = 1;                     // benign same-value race
    __syncthreads();
    const bool is32 = (s_is32 != 0);
    if (tid == 0) g_mask_is32 = is32 ? 1 : 0;

    int kw[8];
    int cnt = 0;
    #pragma unroll
    for (int i = 0; i < 8; i++) {
        int tk = tid * 8 + i;
        int bits = 0;
        #pragma unroll
        for (int w = 0; w < W_SZ; w++) {
            long long mv = is32
                ? (long long)((const int*)mraw)[(size_t)tk * W_SZ + w]
                : ((const long long*)mraw)[(size_t)tk * W_SZ + w];
            if (mv != 0) bits |= (1 << w);
        }
        if (bits == 0) bits = 31;           // all-masked token: keep all 5
        kw[i] = bits;
        cnt += __popc(bits);
    }

    // exclusive scan of cnt over 1024 threads
    const int lane = tid & 31, wrp = tid >> 5;
    int inc = cnt;
    #pragma unroll
    for (int off = 1; off < 32; off <<= 1) {
        int n = __shfl_up_sync(0xffffffff, inc, off);
        if (lane >= off) inc += n;
    }
    if (lane == 31) s_warp[wrp] = inc;
    __syncthreads();
    if (wrp == 0) {
        int wv = s_warp[lane];
        #pragma unroll
        for (int off = 1; off < 32; off <<= 1) {
            int n = __shfl_up_sync(0xffffffff, wv, off);
            if (lane >= off) wv += n;
        }
        s_warp[lane] = wv;                   // inclusive warp sums
    }
    __syncthreads();

    int base = inc - cnt + (wrp ? s_warp[wrp - 1] : 0);
    #pragma unroll
    for (int i = 0; i < 8; i++) {
        int tk = tid * 8 + i;
        int bits = kw[i];
        while (bits) {
            int w = __ffs(bits) - 1;
            bits &= bits - 1;
            g_rowmap[base++] = tk * W_SZ + w;
        }
    }

    if (tid == 1023) {
        int total = base;                    // grand total
        int nb = (total + 127) >> 7;
        g_mc_blocks = nb;
        for (int i = total; i < nb * 128; i++)
            g_rowmap[i] = 0;                 // pad: duplicates row 0 (benign)
    }
}

// ---------------------------------------------------------------------------
// One transpose+convert launch for W1 and W2 (z selects)
// ---------------------------------------------------------------------------
__global__ void trans_all_kernel(const float* __restrict__ W1,
                                 const float* __restrict__ W2)
{
    const int z = blockIdx.z;
    const float* in = z ? W2 : W1;
    bf16* out = z ? g_W2T : g_W1T;
    const int K = z ? H_SZ : D_SZ;
    const int N = H_SZ;
    if (blockIdx.y * 32 >= K) return;

    __shared__ float tile[32][33];
    int x = blockIdx.x * 32 + threadIdx.x;
    int y0 = blockIdx.y * 32;
    #pragma unroll
    for (int j = 0; j < 32; j += 8) {
        int y = y0 + threadIdx.y + j;
        if (y < K && x < N)
            tile[threadIdx.y + j][threadIdx.x] = in[(size_t)y * N + x];
    }
    __syncthreads();
    int ox = y0 + threadIdx.x;
    int oy0 = blockIdx.x * 32;
    #pragma unroll
    for (int j = 0; j < 32; j += 8) {
        int oy = oy0 + threadIdx.y + j;
        if (oy < N && ox < K)
            out[(size_t)oy * K + ox] =
                __float2bfloat16_rn(tile[threadIdx.x][threadIdx.y + j]);
    }
}

// ---------------------------------------------------------------------------
// Shared GEMM machinery
// ---------------------------------------------------------------------------
#define BKQ 64
#define TSTRIDE 72
#define TILE_BF (128 * TSTRIDE)
#define SMEM_BYTES (4 * TILE_BF * 2)     // 73728 B -> 3 CTAs/SM

__device__ __forceinline__ void cp_async16(uint32_t dst, const void* src, int ssize)
{
    asm volatile("cp.async.cg.shared.global [%0], [%1], 16, %2;\n"
                 :: "r"(dst), "l"(src), "r"(ssize));
}
__device__ __forceinline__ void cp_commit() { asm volatile("cp.async.commit_group;\n"); }
__device__ __forceinline__ void cp_wait0()  { asm volatile("cp.async.wait_group 0;\n"); }

#define MMA_BF16(acc, af, bf0, bf1)                                            \
    asm volatile(                                                              \
        "mma.sync.aligned.m16n8k16.row.col.f32.bf16.bf16.f32 "                 \
        "{%0,%1,%2,%3}, {%4,%5,%6,%7}, {%8,%9}, {%0,%1,%2,%3};\n"              \
        : "+f"((acc)[0]), "+f"((acc)[1]), "+f"((acc)[2]), "+f"((acc)[3])       \
        : "r"((af)[0]), "r"((af)[1]), "r"((af)[2]), "r"((af)[3]),              \
          "r"(bf0), "r"(bf1))

#define GEMM_VARS()                                                            \
    const int tid  = threadIdx.x;                                              \
    const int lane = tid & 31;                                                 \
    const int wid  = tid >> 5;                                                 \
    const int wm   = (wid & 1) * 64;                                           \
    const int wn   = (wid >> 1) * 64;                                          \
    const int g    = lane >> 2;                                                \
    const int tg   = lane & 3;                                                 \
    const int crow = tid >> 3;                                                 \
    const int ac   = (tid & 7) * 8;

#define GEMM_BODY(A, Bt, LDA, K, m0, n0)                                       \
    uint32_t as_base[2], bs_base[2];                                           \
    as_base[0] = (uint32_t)__cvta_generic_to_shared(As[0]);                    \
    as_base[1] = (uint32_t)__cvta_generic_to_shared(As[1]);                    \
    bs_base[0] = (uint32_t)__cvta_generic_to_shared(Bs[0]);                    \
    bs_base[1] = (uint32_t)__cvta_generic_to_shared(Bs[1]);                    \
    float acc[4][8][4];                                                        \
    _Pragma("unroll")                                                          \
    for (int mi = 0; mi < 4; mi++)                                             \
        _Pragma("unroll")                                                      \
        for (int ni = 0; ni < 8; ni++)                                         \
            _Pragma("unroll")                                                  \
            for (int r = 0; r < 4; r++)                                        \
                acc[mi][ni][r] = 0.f;                                          \
    const int kt16  = ((K) + 15) >> 4;                                         \
    const int tiles = (kt16 + 3) >> 2;                                         \
    auto load_tile = [&](int buf, int k0) {                                    \
        int gk = k0 + ac;                                                      \
        int ok = (gk < (K)) ? 16 : 0;                                          \
        int gks = ok ? gk : 0;                                                 \
        _Pragma("unroll")                                                      \
        for (int i = 0; i < 8; i++) {                                          \
            int row = crow + 16 * i;                                           \
            cp_async16(as_base[buf] + (row * TSTRIDE + ac) * 2,                \
                       (A) + (size_t)((m0) + row) * (LDA) + gks, ok);          \
        }                                                                      \
        _Pragma("unroll")                                                      \
        for (int i = 0; i < 8; i++) {                                          \
            int row = crow + 16 * i;                                           \
            cp_async16(bs_base[buf] + (row * TSTRIDE + ac) * 2,                \
                       (Bt) + (size_t)((n0) + row) * (LDA) + gks, ok);         \
        }                                                                      \
        cp_commit();                                                           \
    };                                                                         \
    load_tile(0, 0);                                                           \
    int buf = 0;                                                               \
    for (int t = 0; t < tiles; t++) {                                          \
        cp_wait0();                                                            \
        __syncthreads();                                                       \
        if (t + 1 < tiles)                                                     \
            load_tile(buf ^ 1, (t + 1) * BKQ);                                 \
        const bf16* Ab = As[buf];                                              \
        const bf16* Bb = Bs[buf];                                              \
        const int slim = kt16 - (t << 2);                                      \
        _Pragma("unroll")                                                      \
        for (int s = 0; s < 4; s++) {                                          \
            if (s >= slim) break;                                              \
            const int kb = s * 16;                                             \
            uint32_t af[4][4];                                                 \
            _Pragma("unroll")                                                  \
            for (int mi = 0; mi < 4; mi++) {                                   \
                const bf16* p = Ab + (wm + mi * 16 + g) * TSTRIDE + kb + 2 * tg; \
                af[mi][0] = *reinterpret_cast<const uint32_t*>(p);             \
                af[mi][1] = *reinterpret_cast<const uint32_t*>(p + 8 * TSTRIDE); \
                af[mi][2] = *reinterpret_cast<const uint32_t*>(p + 8);         \
                af[mi][3] = *reinterpret_cast<const uint32_t*>(p + 8 * TSTRIDE + 8); \
            }                                                                  \
            uint32_t bfr[8][2];                                                \
            _Pragma("unroll")                                                  \
            for (int ni = 0; ni < 8; ni++) {                                   \
                const bf16* p = Bb + (wn + ni * 8 + g) * TSTRIDE + kb + 2 * tg; \
                bfr[ni][0] = *reinterpret_cast<const uint32_t*>(p);            \
                bfr[ni][1] = *reinterpret_cast<const uint32_t*>(p + 8);        \
            }                                                                  \
            _Pragma("unroll")                                                  \
            for (int mi = 0; mi < 4; mi++)                                     \
                _Pragma("unroll")                                              \
                for (int ni = 0; ni < 8; ni++)                                 \
                    MMA_BF16(acc[mi][ni], af[mi], bfr[ni][0], bfr[ni][1]);     \
        }                                                                      \
        buf ^= 1;                                                              \
    }

// ---------------------------------------------------------------------------
// Wc split-K GEMM + reduce
// ---------------------------------------------------------------------------
__global__ __launch_bounds__(128, 3)
void wc_gemm(void)
{
    extern __shared__ bf16 smem[];
    bf16* As[2] = { smem,                smem + TILE_BF };
    bf16* Bs[2] = { smem + 2 * TILE_BF,  smem + 3 * TILE_BF };
    GEMM_VARS();
    const int m0 = blockIdx.y * 128;
    const int n0 = blockIdx.x * 128;
    const int z  = blockIdx.z;
    const bf16* A  = g_W2B + z * 128;
    const bf16* Bt = g_aWB + z * 128;
    GEMM_BODY(A, Bt, H_SZ, 128, m0, n0);

    float* P = g_wcp + (size_t)z * H_SZ * H_SZ;
    #pragma unroll
    for (int ni = 0; ni < 8; ni++) {
        const int col = n0 + wn + ni * 8 + tg * 2;
        #pragma unroll
        for (int mi = 0; mi < 4; mi++) {
            const int row = m0 + wm + mi * 16 + g;
            *reinterpret_cast<float2*>(&P[(size_t)row * H_SZ + col]) =
                make_float2(acc[mi][ni][0], acc[mi][ni][1]);
            *reinterpret_cast<float2*>(&P[(size_t)(row + 8) * H_SZ + col]) =
                make_float2(acc[mi][ni][2], acc[mi][ni][3]);
        }
    }
}

__global__ void wc_reduce(void)
{
    int i = (blockIdx.x * blockDim.x + threadIdx.x) * 2;
    if (i >= H_SZ * H_SZ) return;
    float2 s = *reinterpret_cast<const float2*>(g_wcp + i);
    #pragma unroll
    for (int z = 1; z < WC_SPLIT; z++) {
        float2 p = *reinterpret_cast<const float2*>(g_wcp + (size_t)z * H_SZ * H_SZ + i);
        s.x += p.x; s.y += p.y;
    }
    *reinterpret_cast<__nv_bfloat162*>(g_WcT + i) = __floats2bfloat162_rn(s.x, s.y);
}

// ---------------------------------------------------------------------------
// GEMM1 (gathered): for compacted rows only; blocks beyond g_mc_blocks exit.
// ---------------------------------------------------------------------------
__global__ __launch_bounds__(128, 3)
void gemm1(const float* __restrict__ b1)
{
    if ((int)blockIdx.y >= g_mc_blocks) return;
    extern __shared__ bf16 smem[];
    bf16* As[2] = { smem,                smem + TILE_BF };
    bf16* Bs[2] = { smem + 2 * TILE_BF,  smem + 3 * TILE_BF };
    GEMM_VARS();
    const int n0 = blockIdx.x * 128;
    const int m0 = blockIdx.y * 128;

    int grow[8];
    #pragma unroll
    for (int i = 0; i < 8; i++)
        grow[i] = g_rowmap[m0 + crow + 16 * i];

    uint32_t as_base[2], bs_base[2];
    as_base[0] = (uint32_t)__cvta_generic_to_shared(As[0]);
    as_base[1] = (uint32_t)__cvta_generic_to_shared(As[1]);
    bs_base[0] = (uint32_t)__cvta_generic_to_shared(Bs[0]);
    bs_base[1] = (uint32_t)__cvta_generic_to_shared(Bs[1]);

    float acc[4][8][4];
    #pragma unroll
    for (int mi = 0; mi < 4; mi++)
        #pragma unroll
        for (int ni = 0; ni < 8; ni++)
            #pragma unroll
            for (int r = 0; r < 4; r++)
                acc[mi][ni][r] = 0.f;

    const int K = D_SZ;
    const int kt16  = (K + 15) >> 4;     // 13
    const int tiles = (kt16 + 3) >> 2;   // 4

    auto load_tile = [&](int buf, int k0) {
        int gk = k0 + ac;
        int ok = (gk < K) ? 16 : 0;
        int gks = ok ? gk : 0;
        #pragma unroll
        for (int i = 0; i < 8; i++) {
            int row = crow + 16 * i;
            cp_async16(as_base[buf] + (row * TSTRIDE + ac) * 2,
                       g_weB + (size_t)grow[i] * K + gks, ok);
        }
        #pragma unroll
        for (int i = 0; i < 8; i++) {
            int row = crow + 16 * i;
            cp_async16(bs_base[buf] + (row * TSTRIDE + ac) * 2,
                       g_W1T + (size_t)(n0 + row) * K + gks, ok);
        }
        cp_commit();
    };

    load_tile(0, 0);
    int buf = 0;
    for (int t = 0; t < tiles; t++) {
        cp_wait0();
        __syncthreads();
        if (t + 1 < tiles)
            load_tile(buf ^ 1, (t + 1) * BKQ);
        const bf16* Ab = As[buf];
        const bf16* Bb = Bs[buf];
        const int slim = kt16 - (t << 2);
        #pragma unroll
        for (int s = 0; s < 4; s++) {
            if (s >= slim) break;
            const int kb = s * 16;
            uint32_t af[4][4];
            #pragma unroll
            for (int mi = 0; mi < 4; mi++) {
                const bf16* p = Ab + (wm + mi * 16 + g) * TSTRIDE + kb + 2 * tg;
                af[mi][0] = *reinterpret_cast<const uint32_t*>(p);
                af[mi][1] = *reinterpret_cast<const uint32_t*>(p + 8 * TSTRIDE);
                af[mi][2] = *reinterpret_cast<const uint32_t*>(p + 8);
                af[mi][3] = *reinterpret_cast<const uint32_t*>(p + 8 * TSTRIDE + 8);
            }
            uint32_t bfr[8][2];
            #pragma unroll
            for (int ni = 0; ni < 8; ni++) {
                const bf16* p = Bb + (wn + ni * 8 + g) * TSTRIDE + kb + 2 * tg;
                bfr[ni][0] = *reinterpret_cast<const uint32_t*>(p);
                bfr[ni][1] = *reinterpret_cast<const uint32_t*>(p + 8);
            }
            #pragma unroll
            for (int mi = 0; mi < 4; mi++)
                #pragma unroll
                for (int ni = 0; ni < 8; ni++)
                    MMA_BF16(acc[mi][ni], af[mi], bfr[ni][0], bfr[ni][1]);
        }
        buf ^= 1;
    }

    #pragma unroll
    for (int ni = 0; ni < 8; ni++) {
        const int col = n0 + wn + ni * 8 + tg * 2;
        const float b0 = b1[col];
        const float bb1 = b1[col + 1];
        #pragma unroll
        for (int mi = 0; mi < 4; mi++) {
            const int lrow = wm + mi * 16 + g;
            const int orow0 = g_rowmap[m0 + lrow];
            const int orow1 = g_rowmap[m0 + lrow + 8];
            float r0 = tanhf(acc[mi][ni][0] + b0);
            float r1 = tanhf(acc[mi][ni][1] + bb1);
            float r2 = tanhf(acc[mi][ni][2] + b0);
            float r3 = tanhf(acc[mi][ni][3] + bb1);
            *reinterpret_cast<__nv_bfloat162*>(&g_tmpB[(size_t)orow0 * H_SZ + col]) =
                __floats2bfloat162_rn(r0, r1);
            *reinterpret_cast<__nv_bfloat162*>(&g_tmpB[(size_t)orow1 * H_SZ + col]) =
                __floats2bfloat162_rn(r2, r3);
        }
    }
}

// ---------------------------------------------------------------------------
// GEMM_r: rB = bf16(loB @ WcT^T), K=768. grid (6, MBQ)
// ---------------------------------------------------------------------------
__global__ __launch_bounds__(128, 3)
void gemm_r(void)
{
    extern __shared__ bf16 smem[];
    bf16* As[2] = { smem,                smem + TILE_BF };
    bf16* Bs[2] = { smem + 2 * TILE_BF,  smem + 3 * TILE_BF };
    GEMM_VARS();
    const int n0 = blockIdx.x * 128;
    const int m0 = blockIdx.y * 128;
    GEMM_BODY(g_loB, g_WcT, H_SZ, H_SZ, m0, n0);

    #pragma unroll
    for (int ni = 0; ni < 8; ni++) {
        const int col = n0 + wn + ni * 8 + tg * 2;
        #pragma unroll
        for (int mi = 0; mi < 4; mi++) {
            const int row = m0 + wm + mi * 16 + g;
            *reinterpret_cast<__nv_bfloat162*>(&g_rB[(size_t)row * H_SZ + col]) =
                __floats2bfloat162_rn(acc[mi][ni][0], acc[mi][ni][1]);
            *reinterpret_cast<__nv_bfloat162*>(&g_rB[(size_t)(row + 8) * H_SZ + col]) =
                __floats2bfloat162_rn(acc[mi][ni][2], acc[mi][ni][3]);
        }
    }
}

// ---------------------------------------------------------------------------
// GEMM_agg: agg = ctx @ W2 + b2 (fp32 out). grid (6, MBQ)
// ---------------------------------------------------------------------------
__global__ __launch_bounds__(128, 3)
void gemm_agg(const float* __restrict__ b2)
{
    extern __shared__ bf16 smem[];
    bf16* As[2] = { smem,                smem + TILE_BF };
    bf16* Bs[2] = { smem + 2 * TILE_BF,  smem + 3 * TILE_BF };
    GEMM_VARS();
    const int n0 = blockIdx.x * 128;
    const int m0 = blockIdx.y * 128;
    GEMM_BODY(g_ctxB, g_W2T, H_SZ, H_SZ, m0, n0);

    #pragma unroll
    for (int ni = 0; ni < 8; ni++) {
        const int col = n0 + wn + ni * 8 + tg * 2;
        const float b0 = b2[col];
        const float bb1 = b2[col + 1];
        #pragma unroll
        for (int mi = 0; mi < 4; mi++) {
            const int row = m0 + wm + mi * 16 + g;
            *reinterpret_cast<float2*>(&g_agg[(size_t)row * H_SZ + col]) =
                make_float2(acc[mi][ni][0] + b0, acc[mi][ni][1] + bb1);
            *reinterpret_cast<float2*>(&g_agg[(size_t)(row + 8) * H_SZ + col]) =
                make_float2(acc[mi][ni][2] + b0, acc[mi][ni][3] + bb1);
        }
    }
}

// ---------------------------------------------------------------------------
// Attention kernel (masked rows of g_tmpB are all-zero; alpha underflows to 0)
// ---------------------------------------------------------------------------
__global__ __launch_bounds__(256)
void attn_kernel(const void* __restrict__ mask, bf16* __restrict__ ctxB)
{
    const int bs  = blockIdx.x;
    const int tid = threadIdx.x;

    __shared__ float red[5][256];
    __shared__ float s_alpha[5];

    const bf16* rrow = g_rB   + (size_t)bs * H_SZ;
    const bf16* trow = g_tmpB + (size_t)bs * W_SZ * H_SZ;

    float rv[3], tv[5][3];
    #pragma unroll
    for (int e = 0; e < 3; e++) {
        int h = tid + e * 256;
        rv[e] = __bfloat162float(rrow[h]);
        #pragma unroll
        for (int w = 0; w < W_SZ; w++)
            tv[w][e] = __bfloat162float(trow[w * H_SZ + h]);
    }

    #pragma unroll
    for (int w = 0; w < W_SZ; w++) {
        float d = 0.f;
        #pragma unroll
        for (int e = 0; e < 3; e++)
            d = fmaf(rv[e], tv[w][e], d);
        red[w][tid] = d;
    }
    __syncthreads();
    for (int s = 128; s > 0; s >>= 1) {
        if (tid < s) {
            #pragma unroll
            for (int w = 0; w < W_SZ; w++)
                red[w][tid] += red[w][tid + s];
        }
        __syncthreads();
    }

    if (tid == 0) {
        const bool is32 = (g_mask_is32 != 0);
        float sc[5];
        float mx = -1e30f;
        #pragma unroll
        for (int w = 0; w < W_SZ; w++) {
            float mk = is32
                ? (float)((const int*)mask)[(size_t)bs * W_SZ + w]
                : (float)((const long long*)mask)[(size_t)bs * W_SZ + w];
            sc[w] = red[w][0] + (1.f - mk) * (-10000.f);
            mx = fmaxf(mx, sc[w]);
        }
        float sum = 0.f;
        #pragma unroll
        for (int w = 0; w < W_SZ; w++) {
            sc[w] = expf(sc[w] - mx);
            sum += sc[w];
        }
        float inv = 1.f / sum;
        #pragma unroll
        for (int w = 0; w < W_SZ; w++)
            s_alpha[w] = sc[w] * inv;
    }
    __syncthreads();

    float alpha[5];
    #pragma unroll
    for (int w = 0; w < W_SZ; w++) alpha[w] = s_alpha[w];

    #pragma unroll
    for (int e = 0; e < 3; e++) {
        int h = tid + e * 256;
        float c = 0.f;
        #pragma unroll
        for (int w = 0; w < W_SZ; w++)
            c = fmaf(alpha[w], tv[w][e], c);
        ctxB[(size_t)bs * H_SZ + h] = __float2bfloat16_rn(c);
    }
}

// ---------------------------------------------------------------------------
// Residual + LayerNorm
// ---------------------------------------------------------------------------
__global__ __launch_bounds__(256)
void ln_kernel(const float* __restrict__ lo,
               const float* __restrict__ gamma,
               const float* __restrict__ beta,
               float* __restrict__ out)
{
    const int bs  = blockIdx.x;
    const int tid = threadIdx.x;

    __shared__ float red0[256], red1[256];

    const float* lorow = lo    + (size_t)bs * H_SZ;
    const float* agrow = g_agg + (size_t)bs * H_SZ;

    float hv[3];
    float psum = 0.f, psq = 0.f;
    #pragma unroll
    for (int e = 0; e < 3; e++) {
        int h = tid + e * 256;
        hv[e] = lorow[h] + agrow[h];
        psum += hv[e];
        psq  = fmaf(hv[e], hv[e], psq);
    }
    red0[tid] = psum;
    red1[tid] = psq;
    __syncthreads();
    for (int s = 128; s > 0; s >>= 1) {
        if (tid < s) {
            red0[tid] += red0[tid + s];
            red1[tid] += red1[tid + s];
        }
        __syncthreads();
    }

    const float inv_h = 1.f / (float)H_SZ;
    float mu   = red0[0] * inv_h;
    float var  = red1[0] * inv_h - mu * mu;
    float rstd = rsqrtf(var + 1e-12f);

    #pragma unroll
    for (int e = 0; e < 3; e++) {
        int h = tid + e * 256;
        out[(size_t)bs * H_SZ + h] = (hv[e] - mu) * rstd * gamma[h] + beta[h];
    }
}

// ---------------------------------------------------------------------------
// Launch: compaction off the critical path, concurrent with conv.
//  s0: memset ─ evStart ─ conv ─ evConv ─ trans ─ (wait evCmp) gemm1 ─
//      (wait evR) attn ─ agg ─ ln
//  s1: (wait evStart) compact ─ evCmp ─ (wait evConv) wc_gemm ─ wc_reduce ─
//      gemm_r ─ evR
// ---------------------------------------------------------------------------
extern "C" void kernel_launch(void* const* d_in, const int* in_sizes, int n_in,
                              void* d_out, int out_size)
{
    const float* lo     = (const float*)d_in[0];
    const float* we_in  = (const float*)d_in[1];
    const void*  mask   = d_in[2];
    const float* W1     = (const float*)d_in[3];
    const float* b1     = (const float*)d_in[4];
    const float* W2     = (const float*)d_in[5];
    const float* b2     = (const float*)d_in[6];
    const float* attn_W = (const float*)d_in[7];
    const float* gamma  = (const float*)d_in[8];
    const float* beta   = (const float*)d_in[9];
    float*       out    = (float*)d_out;

    bf16 *ctxB_p;
    cudaGetSymbolAddress((void**)&ctxB_p, g_ctxB);

    cudaFuncSetAttribute(wc_gemm,  cudaFuncAttributeMaxDynamicSharedMemorySize, SMEM_BYTES);
    cudaFuncSetAttribute(gemm1,    cudaFuncAttributeMaxDynamicSharedMemorySize, SMEM_BYTES);
    cudaFuncSetAttribute(gemm_r,   cudaFuncAttributeMaxDynamicSharedMemorySize, SMEM_BYTES);
    cudaFuncSetAttribute(gemm_agg, cudaFuncAttributeMaxDynamicSharedMemorySize, SMEM_BYTES);

    int* flag_p;
    cudaGetSymbolAddress((void**)&flag_p, g_mask_is32);

    cudaStream_t s1;
    cudaStreamCreateWithFlags(&s1, cudaStreamNonBlocking);
    cudaEvent_t evStart, evConv, evCmp, evR;
    cudaEventCreateWithFlags(&evStart, cudaEventDisableTiming);
    cudaEventCreateWithFlags(&evConv,  cudaEventDisableTiming);
    cudaEventCreateWithFlags(&evCmp,   cudaEventDisableTiming);
    cudaEventCreateWithFlags(&evR,     cudaEventDisableTiming);

    dim3 blk(128);

    // ---- s0: fork point ----
    cudaMemsetAsync(flag_p, 0, sizeof(int));
    cudaEventRecord(evStart, 0);

    // ---- s1: mask compaction (self-contained; concurrent with conv) ----
    cudaStreamWaitEvent(s1, evStart, 0);
    mask_compact<<<1, 1024, 0, s1>>>(mask);
    cudaEventRecord(evCmp, s1);

    // ---- s0: converts ----
    conv_all_kernel<<<CONVB, 256>>>(we_in, lo, W2, attn_W);
    cudaEventRecord(evConv, 0);

    // ---- s1: Wc chain + GEMM_r (needs conv outputs) ----
    cudaStreamWaitEvent(s1, evConv, 0);
    wc_gemm<<<dim3(6, 6, WC_SPLIT), blk, SMEM_BYTES, s1>>>();
    wc_reduce<<<(H_SZ * H_SZ / 2 + 255) / 256, 256, 0, s1>>>();
    gemm_r<<<dim3(6, MBQ), blk, SMEM_BYTES, s1>>>();
    cudaEventRecord(evR, s1);

    // ---- s0: transposes then gathered GEMM1 ----
    {
        dim3 tb(32, 8);
        dim3 tg(24, 24, 2);
        trans_all_kernel<<<tg, tb>>>(W1, W2);
    }
    cudaStreamWaitEvent(0, evCmp, 0);
    gemm1<<<dim3(6, MB1), blk, SMEM_BYTES>>>(b1);

    // ---- join, then the dependent tail ----
    cudaStreamWaitEvent(0, evR, 0);
    attn_kernel<<<MQ, 256>>>(mask, ctxB_p);
    gemm_agg<<<dim3(6, MBQ), blk, SMEM_BYTES>>>(b2);
    ln_kernel<<<MQ, 256>>>(lo, gamma, beta, out);

    cudaStreamDestroy(s1);
    cudaEventDestroy(evStart);
    cudaEventDestroy(evConv);
    cudaEventDestroy(evCmp);
    cudaEventDestroy(evR);
}